// round 12
// baseline (speedup 1.0000x reference)
#include <cuda_runtime.h>
#include <cuda_fp16.h>
#include <cstdint>

// Problem constants
#define BB 8
#define TT 256
#define UU 128
#define HH 512
#define II 640
#define VV 1024

// Scratch (no cudaMalloc allowed)
__device__ float  g_enc_proj[BB * TT * II];   // (2048, 640) fp32
__device__ float  g_dec_proj[BB * UU * II];   // (1024, 640) fp32
__device__ __half g_w_half[VV * II];          // W^T fp16 [v][k]

__device__ __forceinline__ uint32_t smem_u32(const void* p) {
    uint32_t a;
    asm("{ .reg .u64 t; cvta.to.shared.u64 t, %1; cvt.u32.u64 %0, t; }"
        : "=r"(a) : "l"(p));
    return a;
}

// HW tanh: single MUFU op, rel err ~2^-11 (below the fp16 quantization)
__device__ __forceinline__ float tanh_hw(float x) {
    float y;
    asm("tanh.approx.f32 %0, %1;" : "=f"(y) : "f"(x));
    return y;
}

__device__ __forceinline__ void mma16816(float* c,
    uint32_t a0, uint32_t a1, uint32_t a2, uint32_t a3,
    uint32_t b0, uint32_t b1)
{
    asm volatile(
        "mma.sync.aligned.m16n8k16.row.col.f32.f16.f16.f32 "
        "{%0,%1,%2,%3}, {%4,%5,%6,%7}, {%8,%9}, {%0,%1,%2,%3};"
        : "+f"(c[0]), "+f"(c[1]), "+f"(c[2]), "+f"(c[3])
        : "r"(a0), "r"(a1), "r"(a2), "r"(a3), "r"(b0), "r"(b1));
}

__device__ __forceinline__ void ldsm4(uint32_t* r, uint32_t addr) {
    asm volatile("ldmatrix.sync.aligned.m8n8.x4.shared.b16 {%0,%1,%2,%3}, [%4];"
        : "=r"(r[0]), "=r"(r[1]), "=r"(r[2]), "=r"(r[3]) : "r"(addr));
}

// .cg: bypass L1 allocation (W bytes are single-use per CTA)
__device__ __forceinline__ void cp_async16(uint32_t dst, const void* src) {
    asm volatile("cp.async.cg.shared.global [%0], [%1], 16;"
                 :: "r"(dst), "l"(src) : "memory");
}
#define CP_COMMIT() asm volatile("cp.async.commit_group;" ::: "memory")
#define CP_WAIT1()  asm volatile("cp.async.wait_group 1;" ::: "memory")

// ---------------------------------------------------------------------------
// Kernel 1: enc/dec projections. 32x64 tiles, 128 thr, grid 960.
// ---------------------------------------------------------------------------
__global__ __launch_bounds__(128) void proj_kernel(
    const float* __restrict__ enc_h, const float* __restrict__ dec_h,
    const float* __restrict__ enc_w, const float* __restrict__ enc_b,
    const float* __restrict__ dec_w, const float* __restrict__ dec_b)
{
    __shared__ float As[16][36];
    __shared__ float Bs[16][64];

    const int r0 = blockIdx.y * 32;
    const int n0 = blockIdx.x * 64;

    const float* in; const float* w; const float* bias; float* outp;
    if (r0 < BB * TT) {
        in = enc_h + (size_t)r0 * HH; w = enc_w; bias = enc_b;
        outp = g_enc_proj + (size_t)r0 * II;
    } else {
        const int r = r0 - BB * TT;
        in = dec_h + (size_t)r * HH; w = dec_w; bias = dec_b;
        outp = g_dec_proj + (size_t)r * II;
    }

    const int t  = threadIdx.x;
    const int tx = t & 15, ty = t >> 4;
    const int a_row = t >> 2;
    const int a_k4  = (t & 3) * 4;
    const int b_kk  = t >> 4;
    const int b_j4  = (t & 15) * 4;

    float acc[4][4] = {};
    for (int k0 = 0; k0 < HH; k0 += 16) {
        float4 av = *(const float4*)(in + (size_t)a_row * HH + k0 + a_k4);
        As[a_k4 + 0][a_row] = av.x;
        As[a_k4 + 1][a_row] = av.y;
        As[a_k4 + 2][a_row] = av.z;
        As[a_k4 + 3][a_row] = av.w;
        #pragma unroll
        for (int j = 0; j < 2; j++)
            *(float4*)&Bs[b_kk + j * 8][b_j4] =
                *(const float4*)(w + (size_t)(k0 + b_kk + j * 8) * II + n0 + b_j4);
        __syncthreads();
        #pragma unroll
        for (int kk = 0; kk < 16; kk++) {
            float4 a4 = *(const float4*)&As[kk][ty * 4];
            float4 b4 = *(const float4*)&Bs[kk][tx * 4];
            float a[4] = {a4.x, a4.y, a4.z, a4.w};
            float bw[4] = {b4.x, b4.y, b4.z, b4.w};
            #pragma unroll
            for (int i = 0; i < 4; i++)
                #pragma unroll
                for (int j = 0; j < 4; j++)
                    acc[i][j] = fmaf(a[i], bw[j], acc[i][j]);
        }
        __syncthreads();
    }
    float4 bv = *(const float4*)(bias + n0 + tx * 4);
    float bb[4] = {bv.x, bv.y, bv.z, bv.w};
    #pragma unroll
    for (int i = 0; i < 4; i++) {
        float4 o;
        o.x = acc[i][0] + bb[0]; o.y = acc[i][1] + bb[1];
        o.z = acc[i][2] + bb[2]; o.w = acc[i][3] + bb[3];
        *(float4*)(outp + (size_t)(ty * 4 + i) * II + n0 + tx * 4) = o;
    }
}

// ---------------------------------------------------------------------------
// Kernel 2: dense_w (640x1024 [k][v]) -> fp16 W^T [v][k], smem transpose.
// ---------------------------------------------------------------------------
__global__ __launch_bounds__(256) void wsplit_kernel(const float* __restrict__ W) {
    __shared__ float tile[32][33];
    const int v0 = (blockIdx.x & 31) * 32;
    const int k0 = (blockIdx.x >> 5) * 32;
    const int tx = threadIdx.x & 31;
    const int ty = threadIdx.x >> 5;   // 0..7
    #pragma unroll
    for (int i = 0; i < 4; i++) {
        int k = k0 + ty + i * 8;
        tile[ty + i * 8][tx] = W[(size_t)k * VV + v0 + tx];
    }
    __syncthreads();
    #pragma unroll
    for (int i = 0; i < 4; i++) {
        int v = v0 + ty + i * 8;
        g_w_half[(size_t)v * II + k0 + tx] = __float2half(tile[tx][ty + i * 8]);
    }
}

// ---------------------------------------------------------------------------
// Kernel 3: fused joint GEMM. 2 CTAs/SM, warp tile 32x64, BK=32 chunks
// (2x work per barrier vs R10 -> overhead amortized), 3-stage cp.async.cg.
// CTA = 64 u-rows x full V in 8 n-tiles of 128. 128 thr / 4 warps.
// A panel 64x640 fp16 XOR-swizzled (80KB) + 3 x 10KB B stages = 110KB.
// ---------------------------------------------------------------------------
#define A_STRIDE 1280                 // 640*2; XOR-16B swizzle
#define A_PANEL  (64 * A_STRIDE)      // 81920
#define B_STRIDE 80                   // 32*2 + 16B pad (20 words)
#define B_CHUNK  (128 * B_STRIDE)     // 10240
#define NSTAGE   3
#define DYN_SMEM (A_PANEL + NSTAGE * B_CHUNK)  // 112640
#define KCH      20                   // BK=32 chunks per n-tile
#define NCHUNK   160                  // 8 n-tiles * 20 k-chunks

__global__ __launch_bounds__(128, 2) void joint_mma_kernel(
    const float* __restrict__ dense_b, float* __restrict__ out)
{
    extern __shared__ __align__(16) char smem[];
    const uint32_t smb   = smem_u32(smem);
    const uint32_t smb_B = smb + A_PANEL;

    const int tid  = threadIdx.x;
    const int lane = tid & 31;
    const int wid  = tid >> 5;
    const int warp_m = wid & 1;    // 0..1 (M halves of 32)
    const int warp_n = wid >> 1;   // 0..1 (N halves of 64 within 128-tile)

    const int bt    = blockIdx.x >> 1;
    const int urow0 = (blockIdx.x & 1) * 64;
    const int b     = bt >> 8;

    const float* __restrict__ encp = g_enc_proj + (size_t)bt * II;
    const float* __restrict__ decp = g_dec_proj + (size_t)(b * UU + urow0) * II;

    // ---- per-thread cp.async constants: 4 x 16B per chunk (row = tid) ----
    const __half* wt0 = g_w_half + (size_t)tid * II;   // row tid of n-tile 0
    const uint32_t d0 = (uint32_t)tid * B_STRIDE;

    // Prologue BEFORE phase 1: chunks 0 (k=0), 1 (k=32) into stages 0, 1
    #pragma unroll
    for (int q = 0; q < 4; q++)
        cp_async16(smb_B + d0 + q * 16, wt0 + q * 8);
    CP_COMMIT();
    #pragma unroll
    for (int q = 0; q < 4; q++)
        cp_async16(smb_B + B_CHUNK + d0 + q * 16, wt0 + 32 + q * 8);
    CP_COMMIT();

    // ---- Phase 1: A panel 64x640 tanh+fp16, XOR-swizzled stores ----
    {
        const int row = tid >> 1;          // 0..63 (2 threads per row)
        const int kq  = tid & 1;           // 32-col halves of each 64-seg
        const int rsw = row & 7;
        char* rowp = smem + row * A_STRIDE;
        const float* dp = decp + (size_t)row * II;
        #pragma unroll 1
        for (int seg = 0; seg < 10; seg++) {
            const int k = seg * 64 + kq * 32;
            float s[32];
            #pragma unroll
            for (int q = 0; q < 8; q++) {
                float4 d = *(const float4*)(dp + k + q * 4);
                float4 e = *(const float4*)(encp + k + q * 4);
                s[q * 4 + 0] = tanh_hw(d.x + e.x);
                s[q * 4 + 1] = tanh_hw(d.y + e.y);
                s[q * 4 + 2] = tanh_hw(d.z + e.z);
                s[q * 4 + 3] = tanh_hw(d.w + e.w);
            }
            uint32_t h[16];
            #pragma unroll
            for (int q = 0; q < 16; q++) {
                __half2 hh = __floats2half2_rn(s[2 * q], s[2 * q + 1]);
                h[q] = *reinterpret_cast<uint32_t*>(&hh);
            }
            const int ub = seg * 8 + kq * 4;     // 16B unit index
            *(uint4*)(rowp + (((ub + 0) ^ rsw) << 4)) = make_uint4(h[0],  h[1],  h[2],  h[3]);
            *(uint4*)(rowp + (((ub + 1) ^ rsw) << 4)) = make_uint4(h[4],  h[5],  h[6],  h[7]);
            *(uint4*)(rowp + (((ub + 2) ^ rsw) << 4)) = make_uint4(h[8],  h[9],  h[10], h[11]);
            *(uint4*)(rowp + (((ub + 3) ^ rsw) << 4)) = make_uint4(h[12], h[13], h[14], h[15]);
        }
    }

    // ---- per-lane ldmatrix bases ----
    const int a_row = warp_m * 32 + (lane & 15);
    const uint32_t A_row0 = smb + (uint32_t)a_row * A_STRIDE;
    const uint32_t A_row1 = A_row0 + 16 * A_STRIDE;
    const int a_rsw = a_row & 7;           // +16 preserves &7
    const int a_ulane = (lane >> 4);
    // B: 4 n16k16 matrices per k-step across 64 n-rows (R6-proven mapping)
    const uint32_t B_lane = (uint32_t)(warp_n * 64 + ((lane >> 4) << 3) + (lane & 7)) * B_STRIDE
                          + (uint32_t)((lane >> 3) & 1) * 16;

    float acc[2][8][4];
    #pragma unroll
    for (int i = 0; i < 2; i++)
        #pragma unroll
        for (int j = 0; j < 8; j++)
            #pragma unroll
            for (int l = 0; l < 4; l++) acc[i][j][l] = 0.0f;

    CP_WAIT1();        // chunk 0 landed (during phase 1)
    __syncthreads();   // A panel + B chunk 0 ready

    // wrap-around loop state (no div/mod)
    const __half* wp = wt0 + 64;   // prefetch source for chunk 2
    int pk     = 2;                // prefetch k-chunk within n-tile
    int pstage = 2;
    int stage  = 0;
    int kc     = 0;                // k-chunk of current chunk
    int n0cur  = 0;                // current n-tile base column
    int remain = NCHUNK - 2;

    #pragma unroll 1
    for (int c = 0; c < NCHUNK; c++) {
        // prefetch chunk c+2
        if (remain > 0) {
            remain--;
            const uint32_t dstb = smb_B + (uint32_t)pstage * B_CHUNK + d0;
            #pragma unroll
            for (int q = 0; q < 4; q++)
                cp_async16(dstb + q * 16, wp + q * 8);
            wp += 32;
            if (++pk == KCH) { pk = 0; wp += (size_t)128 * II - 640; }
            if (++pstage == NSTAGE) pstage = 0;
        }
        CP_COMMIT();

        // ---- MMA on chunk c (BK=32: two k16 steps) ----
        const uint32_t Bbase = smb_B + (uint32_t)stage * B_CHUNK + B_lane;
        const int ub = kc * 4 + a_ulane;
        #pragma unroll
        for (int ks = 0; ks < 2; ks++) {
            const int u = ub + ks * 2;
            const uint32_t a_off = (uint32_t)((u ^ a_rsw) << 4);
            uint32_t a0[4], a1[4];
            ldsm4(a0, A_row0 + a_off);
            ldsm4(a1, A_row1 + a_off);
            uint32_t bf[4][4];
            #pragma unroll
            for (int ntp = 0; ntp < 4; ntp++)
                ldsm4(bf[ntp], Bbase + ntp * (16 * B_STRIDE) + ks * 32);
            #pragma unroll
            for (int ntp = 0; ntp < 4; ntp++) {
                mma16816(acc[0][2 * ntp + 0], a0[0], a0[1], a0[2], a0[3], bf[ntp][0], bf[ntp][1]);
                mma16816(acc[0][2 * ntp + 1], a0[0], a0[1], a0[2], a0[3], bf[ntp][2], bf[ntp][3]);
                mma16816(acc[1][2 * ntp + 0], a1[0], a1[1], a1[2], a1[3], bf[ntp][0], bf[ntp][1]);
                mma16816(acc[1][2 * ntp + 1], a1[0], a1[1], a1[2], a1[3], bf[ntp][2], bf[ntp][3]);
            }
        }

        // ---- epilogue at n-tile boundary ----
        if (kc == KCH - 1) {
            #pragma unroll
            for (int mt = 0; mt < 2; mt++) {
                const int r = warp_m * 32 + mt * 16 + (lane >> 2);
                float* o0 = out + ((size_t)bt * 128 + urow0 + r) * VV;
                #pragma unroll
                for (int nt = 0; nt < 8; nt++) {
                    const int col = n0cur + warp_n * 64 + nt * 8 + (lane & 3) * 2;
                    float2 bb = *(const float2*)(dense_b + col);
                    float2 v0 = make_float2(acc[mt][nt][0] + bb.x, acc[mt][nt][1] + bb.y);
                    float2 v1 = make_float2(acc[mt][nt][2] + bb.x, acc[mt][nt][3] + bb.y);
                    *(float2*)(o0 + col) = v0;
                    *(float2*)(o0 + (size_t)8 * VV + col) = v1;
                    #pragma unroll
                    for (int l = 0; l < 4; l++) acc[mt][nt][l] = 0.0f;
                }
            }
            n0cur += 128;
            kc = -1;
        }
        kc++;
        if (++stage == NSTAGE) stage = 0;

        CP_WAIT1();      // chunk c+1 landed (newest group may be in flight)
        __syncthreads(); // publish + protect stage reuse
    }
}

// ---------------------------------------------------------------------------
extern "C" void kernel_launch(void* const* d_in, const int* in_sizes, int n_in,
                              void* d_out, int out_size) {
    const float* enc_h   = (const float*)d_in[0];
    const float* dec_h   = (const float*)d_in[1];
    const float* enc_w   = (const float*)d_in[2];
    const float* enc_b   = (const float*)d_in[3];
    const float* dec_w   = (const float*)d_in[4];
    const float* dec_b   = (const float*)d_in[5];
    const float* dense_w = (const float*)d_in[6];
    const float* dense_b = (const float*)d_in[7];
    float* out = (float*)d_out;

    static bool attr_set = false;
    if (!attr_set) {
        cudaFuncSetAttribute(joint_mma_kernel,
                             cudaFuncAttributeMaxDynamicSharedMemorySize, DYN_SMEM);
        attr_set = true;
    }

    proj_kernel<<<dim3(10, 96), 128>>>(enc_h, dec_h, enc_w, enc_b, dec_w, dec_b);
    wsplit_kernel<<<640, 256>>>(dense_w);
    // 4096 CTAs: (bt, u-half); each covers full V. 2 CTAs resident per SM.
    joint_mma_kernel<<<4096, 128, DYN_SMEM>>>(dense_b, out);
}

// round 13
// speedup vs baseline: 1.0745x; 1.0745x over previous
#include <cuda_runtime.h>
#include <cuda_fp16.h>
#include <cstdint>

// Problem constants
#define BB 8
#define TT 256
#define UU 128
#define HH 512
#define II 640
#define VV 1024

// Scratch (no cudaMalloc allowed)
__device__ float  g_enc_proj[BB * TT * II];   // (2048, 640) fp32
__device__ float  g_dec_proj[BB * UU * II];   // (1024, 640) fp32
__device__ __half g_w_half[VV * II];          // W^T fp16 [v][k]

__device__ __forceinline__ uint32_t smem_u32(const void* p) {
    uint32_t a;
    asm("{ .reg .u64 t; cvta.to.shared.u64 t, %1; cvt.u32.u64 %0, t; }"
        : "=r"(a) : "l"(p));
    return a;
}

// HW tanh: single MUFU op, rel err ~2^-11 (below the fp16 quantization)
__device__ __forceinline__ float tanh_hw(float x) {
    float y;
    asm("tanh.approx.f32 %0, %1;" : "=f"(y) : "f"(x));
    return y;
}

__device__ __forceinline__ void mma16816(float* c,
    uint32_t a0, uint32_t a1, uint32_t a2, uint32_t a3,
    uint32_t b0, uint32_t b1)
{
    asm volatile(
        "mma.sync.aligned.m16n8k16.row.col.f32.f16.f16.f32 "
        "{%0,%1,%2,%3}, {%4,%5,%6,%7}, {%8,%9}, {%0,%1,%2,%3};"
        : "+f"(c[0]), "+f"(c[1]), "+f"(c[2]), "+f"(c[3])
        : "r"(a0), "r"(a1), "r"(a2), "r"(a3), "r"(b0), "r"(b1));
}

__device__ __forceinline__ void ldsm4(uint32_t* r, uint32_t addr) {
    asm volatile("ldmatrix.sync.aligned.m8n8.x4.shared.b16 {%0,%1,%2,%3}, [%4];"
        : "=r"(r[0]), "=r"(r[1]), "=r"(r[2]), "=r"(r[3]) : "r"(addr));
}

// .cg: bypass L1 allocation (W bytes are single-use per CTA)
__device__ __forceinline__ void cp_async16(uint32_t dst, const void* src) {
    asm volatile("cp.async.cg.shared.global [%0], [%1], 16;"
                 :: "r"(dst), "l"(src) : "memory");
}
#define CP_COMMIT() asm volatile("cp.async.commit_group;" ::: "memory")
#define CP_WAIT1()  asm volatile("cp.async.wait_group 1;" ::: "memory")

// ---------------------------------------------------------------------------
// Kernel 1: enc/dec projections. 32x64 tiles, 128 thr, grid 960.
// ---------------------------------------------------------------------------
__global__ __launch_bounds__(128) void proj_kernel(
    const float* __restrict__ enc_h, const float* __restrict__ dec_h,
    const float* __restrict__ enc_w, const float* __restrict__ enc_b,
    const float* __restrict__ dec_w, const float* __restrict__ dec_b)
{
    __shared__ float As[16][36];
    __shared__ float Bs[16][64];

    const int r0 = blockIdx.y * 32;
    const int n0 = blockIdx.x * 64;

    const float* in; const float* w; const float* bias; float* outp;
    if (r0 < BB * TT) {
        in = enc_h + (size_t)r0 * HH; w = enc_w; bias = enc_b;
        outp = g_enc_proj + (size_t)r0 * II;
    } else {
        const int r = r0 - BB * TT;
        in = dec_h + (size_t)r * HH; w = dec_w; bias = dec_b;
        outp = g_dec_proj + (size_t)r * II;
    }

    const int t  = threadIdx.x;
    const int tx = t & 15, ty = t >> 4;
    const int a_row = t >> 2;
    const int a_k4  = (t & 3) * 4;
    const int b_kk  = t >> 4;
    const int b_j4  = (t & 15) * 4;

    float acc[4][4] = {};
    for (int k0 = 0; k0 < HH; k0 += 16) {
        float4 av = *(const float4*)(in + (size_t)a_row * HH + k0 + a_k4);
        As[a_k4 + 0][a_row] = av.x;
        As[a_k4 + 1][a_row] = av.y;
        As[a_k4 + 2][a_row] = av.z;
        As[a_k4 + 3][a_row] = av.w;
        #pragma unroll
        for (int j = 0; j < 2; j++)
            *(float4*)&Bs[b_kk + j * 8][b_j4] =
                *(const float4*)(w + (size_t)(k0 + b_kk + j * 8) * II + n0 + b_j4);
        __syncthreads();
        #pragma unroll
        for (int kk = 0; kk < 16; kk++) {
            float4 a4 = *(const float4*)&As[kk][ty * 4];
            float4 b4 = *(const float4*)&Bs[kk][tx * 4];
            float a[4] = {a4.x, a4.y, a4.z, a4.w};
            float bw[4] = {b4.x, b4.y, b4.z, b4.w};
            #pragma unroll
            for (int i = 0; i < 4; i++)
                #pragma unroll
                for (int j = 0; j < 4; j++)
                    acc[i][j] = fmaf(a[i], bw[j], acc[i][j]);
        }
        __syncthreads();
    }
    float4 bv = *(const float4*)(bias + n0 + tx * 4);
    float bb[4] = {bv.x, bv.y, bv.z, bv.w};
    #pragma unroll
    for (int i = 0; i < 4; i++) {
        float4 o;
        o.x = acc[i][0] + bb[0]; o.y = acc[i][1] + bb[1];
        o.z = acc[i][2] + bb[2]; o.w = acc[i][3] + bb[3];
        *(float4*)(outp + (size_t)(ty * 4 + i) * II + n0 + tx * 4) = o;
    }
}

// ---------------------------------------------------------------------------
// Kernel 2: dense_w (640x1024 [k][v]) -> fp16 W^T [v][k], smem transpose.
// ---------------------------------------------------------------------------
__global__ __launch_bounds__(256) void wsplit_kernel(const float* __restrict__ W) {
    __shared__ float tile[32][33];
    const int v0 = (blockIdx.x & 31) * 32;
    const int k0 = (blockIdx.x >> 5) * 32;
    const int tx = threadIdx.x & 31;
    const int ty = threadIdx.x >> 5;   // 0..7
    #pragma unroll
    for (int i = 0; i < 4; i++) {
        int k = k0 + ty + i * 8;
        tile[ty + i * 8][tx] = W[(size_t)k * VV + v0 + tx];
    }
    __syncthreads();
    #pragma unroll
    for (int i = 0; i < 4; i++) {
        int v = v0 + ty + i * 8;
        g_w_half[(size_t)v * II + k0 + tx] = __float2half(tile[tx][ty + i * 8]);
    }
}

// ---------------------------------------------------------------------------
// Kernel 3: fused joint GEMM — R10 skeleton (2 CTAs/SM, 256 thr / 8 warps,
// warp tile 32x64, BK=16) with XOR-swizzled B (no pad, 8KB/stage) enabling
// a 3-stage pipeline: prefetch distance 2 chunks, wait_group 1 never blocks.
// CTA = 64 u-rows x full V=1024 in 4 n-tiles of 256.
// A panel 64x640 fp16 XOR-swizzled (80KB) + 3 x 8KB B = 106496B.
// ---------------------------------------------------------------------------
#define A_STRIDE 1280                 // 640*2; XOR-16B swizzle
#define A_PANEL  (64 * A_STRIDE)      // 81920
#define B_STRIDE 32                   // 16*2, no pad; XOR swizzle q^=(r>>2)&1
#define B_CHUNK  (256 * B_STRIDE)     // 8192
#define NSTAGE   3
#define DYN_SMEM (A_PANEL + NSTAGE * B_CHUNK)  // 106496
#define KCH      40                   // k-chunks per n-tile (640/16)
#define NCHUNK   160                  // 4 n-tiles * 40 k-chunks

__global__ __launch_bounds__(256, 2) void joint_mma_kernel(
    const float* __restrict__ dense_b, float* __restrict__ out)
{
    extern __shared__ __align__(16) char smem[];
    const uint32_t smb   = smem_u32(smem);
    const uint32_t smb_B = smb + A_PANEL;

    const int tid  = threadIdx.x;
    const int lane = tid & 31;
    const int wid  = tid >> 5;
    const int warp_m = wid & 1;    // 0..1 (M halves of 32)
    const int warp_n = wid >> 1;   // 0..3 (N quarters of 64 within 256-tile)

    const int bt    = blockIdx.x >> 1;
    const int urow0 = (blockIdx.x & 1) * 64;
    const int b     = bt >> 8;

    const float* __restrict__ encp = g_enc_proj + (size_t)bt * II;
    const float* __restrict__ decp = g_dec_proj + (size_t)(b * UU + urow0) * II;

    // ---- per-thread cp.async constants: row = tid, 2 x 16B per chunk ----
    // dst swizzle: unit q at row r lands at r*32 + ((q ^ ((r>>2)&1))<<4)
    const uint32_t swt = ((uint32_t)(tid >> 2) & 1u) << 4;
    const uint32_t dqa = (uint32_t)tid * B_STRIDE + swt;          // q=0
    const uint32_t dqb = (uint32_t)tid * B_STRIDE + (swt ^ 16u);  // q=1
    const __half* wt0 = g_w_half + (size_t)tid * II;   // row tid of n-tile 0

    // Prologue BEFORE phase 1: chunks 0 (k=0), 1 (k=16) into stages 0, 1
    cp_async16(smb_B + dqa, wt0);
    cp_async16(smb_B + dqb, wt0 + 8);
    CP_COMMIT();
    cp_async16(smb_B + B_CHUNK + dqa, wt0 + 16);
    cp_async16(smb_B + B_CHUNK + dqb, wt0 + 24);
    CP_COMMIT();

    // ---- Phase 1: A panel 64x640 tanh+fp16, XOR-swizzled stores ----
    {
        const int row = tid >> 2;          // 0..63
        const int kq  = tid & 3;
        const int rsw = row & 7;
        char* rowp = smem + row * A_STRIDE;
        const float* dp = decp + (size_t)row * II;
        #pragma unroll 1
        for (int seg = 0; seg < 10; seg++) {
            const int k = seg * 64 + kq * 16;
            float s[16];
            #pragma unroll
            for (int q = 0; q < 4; q++) {
                float4 d = *(const float4*)(dp + k + q * 4);
                float4 e = *(const float4*)(encp + k + q * 4);
                s[q * 4 + 0] = tanh_hw(d.x + e.x);
                s[q * 4 + 1] = tanh_hw(d.y + e.y);
                s[q * 4 + 2] = tanh_hw(d.z + e.z);
                s[q * 4 + 3] = tanh_hw(d.w + e.w);
            }
            uint32_t h[8];
            #pragma unroll
            for (int q = 0; q < 8; q++) {
                __half2 hh = __floats2half2_rn(s[2 * q], s[2 * q + 1]);
                h[q] = *reinterpret_cast<uint32_t*>(&hh);
            }
            const int ub = seg * 8 + kq * 2;     // 16B unit index
            *(uint4*)(rowp + (((ub + 0) ^ rsw) << 4)) = make_uint4(h[0], h[1], h[2], h[3]);
            *(uint4*)(rowp + (((ub + 1) ^ rsw) << 4)) = make_uint4(h[4], h[5], h[6], h[7]);
        }
    }

    // ---- per-lane ldmatrix bases ----
    const int a_row = warp_m * 32 + (lane & 15);
    const uint32_t A_row0 = smb + (uint32_t)a_row * A_STRIDE;
    const uint32_t A_row1 = A_row0 + 16 * A_STRIDE;
    const int a_rsw = a_row & 7;           // +16 preserves &7
    const int a_ulane = (lane >> 4);
    // B: row rB = warp_n*64 + ((lane>>4)<<3) + (lane&7); q = (lane>>3)&1;
    // swizzled: banks {0,8,16,24,4,12,20,28} per 8-row phase -> conflict-free.
    const int rB = warp_n * 64 + ((lane >> 4) << 3) + (lane & 7);
    const uint32_t B_lane = (uint32_t)rB * B_STRIDE
        + ((((uint32_t)(lane >> 3) & 1u) ^ ((uint32_t)(rB >> 2) & 1u)) << 4);

    float acc[2][8][4];
    #pragma unroll
    for (int i = 0; i < 2; i++)
        #pragma unroll
        for (int j = 0; j < 8; j++)
            #pragma unroll
            for (int l = 0; l < 4; l++) acc[i][j][l] = 0.0f;

    CP_WAIT1();        // chunk 0 landed (during phase 1)
    __syncthreads();   // A panel + B chunk 0 ready

    // wrap-around loop state (no div/mod)
    const __half* wp = wt0 + 32;   // prefetch source for chunk 2 (k=32)
    int pk     = 2;                // prefetch k-chunk within n-tile
    int pstage = 2;
    int stage  = 0;
    int kc     = 0;                // k-chunk of current chunk
    int n0cur  = 0;                // current n-tile base column
    int remain = NCHUNK - 2;

    #pragma unroll 1
    for (int c = 0; c < NCHUNK; c++) {
        // prefetch chunk c+2 (stage freed by the sync at end of iter c-1)
        if (remain > 0) {
            remain--;
            const uint32_t dstb = smb_B + (uint32_t)pstage * B_CHUNK;
            cp_async16(dstb + dqa, wp);
            cp_async16(dstb + dqb, wp + 8);
            wp += 16;
            if (++pk == KCH) { pk = 0; wp += (size_t)256 * II - 640; }
            if (++pstage == NSTAGE) pstage = 0;
        }
        CP_COMMIT();

        // ---- MMA on chunk c (one k16 step, warp tile 32x64) ----
        const uint32_t Bbase = smb_B + (uint32_t)stage * B_CHUNK + B_lane;
        const int u = kc * 2 + a_ulane;
        const uint32_t a_off = (uint32_t)((u ^ a_rsw) << 4);
        uint32_t a0[4], a1[4];
        ldsm4(a0, A_row0 + a_off);
        ldsm4(a1, A_row1 + a_off);
        uint32_t bf[4][4];
        #pragma unroll
        for (int ntp = 0; ntp < 4; ntp++)
            ldsm4(bf[ntp], Bbase + ntp * (16 * B_STRIDE));
        #pragma unroll
        for (int ntp = 0; ntp < 4; ntp++) {
            mma16816(acc[0][2 * ntp + 0], a0[0], a0[1], a0[2], a0[3], bf[ntp][0], bf[ntp][1]);
            mma16816(acc[0][2 * ntp + 1], a0[0], a0[1], a0[2], a0[3], bf[ntp][2], bf[ntp][3]);
            mma16816(acc[1][2 * ntp + 0], a1[0], a1[1], a1[2], a1[3], bf[ntp][0], bf[ntp][1]);
            mma16816(acc[1][2 * ntp + 1], a1[0], a1[1], a1[2], a1[3], bf[ntp][2], bf[ntp][3]);
        }

        // ---- epilogue at n-tile boundary ----
        if (kc == KCH - 1) {
            #pragma unroll
            for (int mt = 0; mt < 2; mt++) {
                const int r = warp_m * 32 + mt * 16 + (lane >> 2);
                float* o0 = out + ((size_t)bt * 128 + urow0 + r) * VV;
                #pragma unroll
                for (int nt = 0; nt < 8; nt++) {
                    const int col = n0cur + warp_n * 64 + nt * 8 + (lane & 3) * 2;
                    float2 bb = *(const float2*)(dense_b + col);
                    float2 v0 = make_float2(acc[mt][nt][0] + bb.x, acc[mt][nt][1] + bb.y);
                    float2 v1 = make_float2(acc[mt][nt][2] + bb.x, acc[mt][nt][3] + bb.y);
                    *(float2*)(o0 + col) = v0;
                    *(float2*)(o0 + (size_t)8 * VV + col) = v1;
                    #pragma unroll
                    for (int l = 0; l < 4; l++) acc[mt][nt][l] = 0.0f;
                }
            }
            n0cur += 256;
            kc = -1;
        }
        kc++;
        if (++stage == NSTAGE) stage = 0;

        CP_WAIT1();      // chunk c+1 landed (c+2 still in flight)
        __syncthreads(); // publish + protect stage reuse
    }
}

// ---------------------------------------------------------------------------
extern "C" void kernel_launch(void* const* d_in, const int* in_sizes, int n_in,
                              void* d_out, int out_size) {
    const float* enc_h   = (const float*)d_in[0];
    const float* dec_h   = (const float*)d_in[1];
    const float* enc_w   = (const float*)d_in[2];
    const float* enc_b   = (const float*)d_in[3];
    const float* dec_w   = (const float*)d_in[4];
    const float* dec_b   = (const float*)d_in[5];
    const float* dense_w = (const float*)d_in[6];
    const float* dense_b = (const float*)d_in[7];
    float* out = (float*)d_out;

    static bool attr_set = false;
    if (!attr_set) {
        cudaFuncSetAttribute(joint_mma_kernel,
                             cudaFuncAttributeMaxDynamicSharedMemorySize, DYN_SMEM);
        attr_set = true;
    }

    proj_kernel<<<dim3(10, 96), 128>>>(enc_h, dec_h, enc_w, enc_b, dec_w, dec_b);
    wsplit_kernel<<<640, 256>>>(dense_w);
    // 4096 CTAs: (bt, u-half); each covers full V. 2 CTAs resident per SM.
    joint_mma_kernel<<<4096, 256, DYN_SMEM>>>(dense_b, out);
}

// round 15
// speedup vs baseline: 1.2443x; 1.1579x over previous
#include <cuda_runtime.h>
#include <cuda_fp16.h>
#include <cstdint>

// Problem constants
#define BB 8
#define TT 256
#define UU 128
#define HH 512
#define II 640
#define VV 1024

// Scratch (no cudaMalloc allowed)
__device__ float  g_enc_proj[BB * TT * II];   // (2048, 640) fp32
__device__ float  g_dec_proj[BB * UU * II];   // (1024, 640) fp32
__device__ __half g_w_half[VV * II];          // W^T fp16 [v][k]

__device__ __forceinline__ uint32_t smem_u32(const void* p) {
    uint32_t a;
    asm("{ .reg .u64 t; cvta.to.shared.u64 t, %1; cvt.u32.u64 %0, t; }"
        : "=r"(a) : "l"(p));
    return a;
}

// HW tanh: single MUFU op, rel err ~2^-11 (below the fp16 quantization)
__device__ __forceinline__ float tanh_hw(float x) {
    float y;
    asm("tanh.approx.f32 %0, %1;" : "=f"(y) : "f"(x));
    return y;
}

__device__ __forceinline__ void mma16816(float* c,
    uint32_t a0, uint32_t a1, uint32_t a2, uint32_t a3,
    uint32_t b0, uint32_t b1)
{
    asm volatile(
        "mma.sync.aligned.m16n8k16.row.col.f32.f16.f16.f32 "
        "{%0,%1,%2,%3}, {%4,%5,%6,%7}, {%8,%9}, {%0,%1,%2,%3};"
        : "+f"(c[0]), "+f"(c[1]), "+f"(c[2]), "+f"(c[3])
        : "r"(a0), "r"(a1), "r"(a2), "r"(a3), "r"(b0), "r"(b1));
}

__device__ __forceinline__ void ldsm4(uint32_t* r, uint32_t addr) {
    asm volatile("ldmatrix.sync.aligned.m8n8.x4.shared.b16 {%0,%1,%2,%3}, [%4];"
        : "=r"(r[0]), "=r"(r[1]), "=r"(r[2]), "=r"(r[3]) : "r"(addr));
}

// .cg: bypass L1 allocation (W bytes are single-use per CTA)
__device__ __forceinline__ void cp_async16(uint32_t dst, const void* src) {
    asm volatile("cp.async.cg.shared.global [%0], [%1], 16;"
                 :: "r"(dst), "l"(src) : "memory");
}
#define CP_COMMIT() asm volatile("cp.async.commit_group;" ::: "memory")
#define CP_WAIT0()  asm volatile("cp.async.wait_group 0;" ::: "memory")

// ---------------------------------------------------------------------------
// Kernel 1: enc/dec projections. 32x64 tiles, 128 thr, grid 960.
// ---------------------------------------------------------------------------
__global__ __launch_bounds__(128) void proj_kernel(
    const float* __restrict__ enc_h, const float* __restrict__ dec_h,
    const float* __restrict__ enc_w, const float* __restrict__ enc_b,
    const float* __restrict__ dec_w, const float* __restrict__ dec_b)
{
    __shared__ float As[16][36];
    __shared__ float Bs[16][64];

    const int r0 = blockIdx.y * 32;
    const int n0 = blockIdx.x * 64;

    const float* in; const float* w; const float* bias; float* outp;
    if (r0 < BB * TT) {
        in = enc_h + (size_t)r0 * HH; w = enc_w; bias = enc_b;
        outp = g_enc_proj + (size_t)r0 * II;
    } else {
        const int r = r0 - BB * TT;
        in = dec_h + (size_t)r * HH; w = dec_w; bias = dec_b;
        outp = g_dec_proj + (size_t)r * II;
    }

    const int t  = threadIdx.x;
    const int tx = t & 15, ty = t >> 4;
    const int a_row = t >> 2;
    const int a_k4  = (t & 3) * 4;
    const int b_kk  = t >> 4;
    const int b_j4  = (t & 15) * 4;

    float acc[4][4] = {};
    for (int k0 = 0; k0 < HH; k0 += 16) {
        float4 av = *(const float4*)(in + (size_t)a_row * HH + k0 + a_k4);
        As[a_k4 + 0][a_row] = av.x;
        As[a_k4 + 1][a_row] = av.y;
        As[a_k4 + 2][a_row] = av.z;
        As[a_k4 + 3][a_row] = av.w;
        #pragma unroll
        for (int j = 0; j < 2; j++)
            *(float4*)&Bs[b_kk + j * 8][b_j4] =
                *(const float4*)(w + (size_t)(k0 + b_kk + j * 8) * II + n0 + b_j4);
        __syncthreads();
        #pragma unroll
        for (int kk = 0; kk < 16; kk++) {
            float4 a4 = *(const float4*)&As[kk][ty * 4];
            float4 b4 = *(const float4*)&Bs[kk][tx * 4];
            float a[4] = {a4.x, a4.y, a4.z, a4.w};
            float bw[4] = {b4.x, b4.y, b4.z, b4.w};
            #pragma unroll
            for (int i = 0; i < 4; i++)
                #pragma unroll
                for (int j = 0; j < 4; j++)
                    acc[i][j] = fmaf(a[i], bw[j], acc[i][j]);
        }
        __syncthreads();
    }
    float4 bv = *(const float4*)(bias + n0 + tx * 4);
    float bb[4] = {bv.x, bv.y, bv.z, bv.w};
    #pragma unroll
    for (int i = 0; i < 4; i++) {
        float4 o;
        o.x = acc[i][0] + bb[0]; o.y = acc[i][1] + bb[1];
        o.z = acc[i][2] + bb[2]; o.w = acc[i][3] + bb[3];
        *(float4*)(outp + (size_t)(ty * 4 + i) * II + n0 + tx * 4) = o;
    }
}

// ---------------------------------------------------------------------------
// Kernel 2: dense_w (640x1024 [k][v]) -> fp16 W^T [v][k], smem transpose.
// ---------------------------------------------------------------------------
__global__ __launch_bounds__(256) void wsplit_kernel(const float* __restrict__ W) {
    __shared__ float tile[32][33];
    const int v0 = (blockIdx.x & 31) * 32;
    const int k0 = (blockIdx.x >> 5) * 32;
    const int tx = threadIdx.x & 31;
    const int ty = threadIdx.x >> 5;   // 0..7
    #pragma unroll
    for (int i = 0; i < 4; i++) {
        int k = k0 + ty + i * 8;
        tile[ty + i * 8][tx] = W[(size_t)k * VV + v0 + tx];
    }
    __syncthreads();
    #pragma unroll
    for (int i = 0; i < 4; i++) {
        int v = v0 + ty + i * 8;
        g_w_half[(size_t)v * II + k0 + tx] = __float2half(tile[tx][ty + i * 8]);
    }
}

// ---------------------------------------------------------------------------
// Kernel 3: fused joint GEMM — R10 skeleton (2 CTAs/SM, 256 thr / 8 warps,
// warp tile 32x64, BK=16, 2-stage B_STRIDE=48) + register double-buffered
// B fragments: ldsm of chunk m+1 issues during chunk m's MMAs, breaking the
// SM-wide LDSM/HMMA phase serialization. R14 bug fixed: a __syncthreads()
// after the chunk-0 fragment preload orders all preload reads before the
// iter-0 cp.async overwrite of stage 0.
// ---------------------------------------------------------------------------
#define A_STRIDE 1280                 // 640*2; XOR-16B swizzle
#define A_PANEL  (64 * A_STRIDE)      // 81920
#define B_STRIDE 48                   // 16*2 + 16B pad (12 words)
#define B_CHUNK  (256 * B_STRIDE)     // 12288
#define DYN_SMEM (A_PANEL + 2 * B_CHUNK)  // 106496
#define KCH      40                   // k-chunks per n-tile (640/16)
#define NCHUNK   160                  // 4 n-tiles * 40 k-chunks

__global__ __launch_bounds__(256, 2) void joint_mma_kernel(
    const float* __restrict__ dense_b, float* __restrict__ out)
{
    extern __shared__ __align__(16) char smem[];
    const uint32_t smb   = smem_u32(smem);
    const uint32_t smb_B = smb + A_PANEL;

    const int tid  = threadIdx.x;
    const int lane = tid & 31;
    const int wid  = tid >> 5;
    const int warp_m = wid & 1;    // 0..1 (M halves of 32)
    const int warp_n = wid >> 1;   // 0..3 (N quarters of 64 within 256-tile)

    const int bt    = blockIdx.x >> 1;
    const int urow0 = (blockIdx.x & 1) * 64;
    const int b     = bt >> 8;

    const float* __restrict__ encp = g_enc_proj + (size_t)bt * II;
    const float* __restrict__ decp = g_dec_proj + (size_t)(b * UU + urow0) * II;

    // ---- per-thread cp.async constants: 2 x 16B per chunk (row = tid>>1) ----
    const int nl0 = tid >> 1;
    const int q0  = tid & 1;
    const __half* wt0 = g_w_half + (size_t)nl0 * II + q0 * 8;
    const uint32_t d0 = (uint32_t)nl0 * B_STRIDE + q0 * 16;

    // Prologue BEFORE phase 1: chunk 0 -> stage 0, chunk 1 -> stage 1
    cp_async16(smb_B + d0,                  wt0);
    cp_async16(smb_B + d0 + 128 * B_STRIDE, wt0 + (size_t)128 * II);
    CP_COMMIT();
    cp_async16(smb_B + B_CHUNK + d0,                  wt0 + 16);
    cp_async16(smb_B + B_CHUNK + d0 + 128 * B_STRIDE, wt0 + (size_t)128 * II + 16);
    CP_COMMIT();

    // ---- Phase 1: A panel 64x640 tanh+fp16, XOR-swizzled stores ----
    {
        const int row = tid >> 2;          // 0..63
        const int kq  = tid & 3;
        const int rsw = row & 7;
        char* rowp = smem + row * A_STRIDE;
        const float* dp = decp + (size_t)row * II;
        #pragma unroll 1
        for (int seg = 0; seg < 10; seg++) {
            const int k = seg * 64 + kq * 16;
            float s[16];
            #pragma unroll
            for (int q = 0; q < 4; q++) {
                float4 d = *(const float4*)(dp + k + q * 4);
                float4 e = *(const float4*)(encp + k + q * 4);
                s[q * 4 + 0] = tanh_hw(d.x + e.x);
                s[q * 4 + 1] = tanh_hw(d.y + e.y);
                s[q * 4 + 2] = tanh_hw(d.z + e.z);
                s[q * 4 + 3] = tanh_hw(d.w + e.w);
            }
            uint32_t h[8];
            #pragma unroll
            for (int q = 0; q < 8; q++) {
                __half2 hh = __floats2half2_rn(s[2 * q], s[2 * q + 1]);
                h[q] = *reinterpret_cast<uint32_t*>(&hh);
            }
            const int ub = seg * 8 + kq * 2;     // 16B unit index
            *(uint4*)(rowp + (((ub + 0) ^ rsw) << 4)) = make_uint4(h[0], h[1], h[2], h[3]);
            *(uint4*)(rowp + (((ub + 1) ^ rsw) << 4)) = make_uint4(h[4], h[5], h[6], h[7]);
        }
    }

    // ---- per-lane ldmatrix bases ----
    const int a_row = warp_m * 32 + (lane & 15);
    const uint32_t A_row0 = smb + (uint32_t)a_row * A_STRIDE;
    const uint32_t A_row1 = A_row0 + 16 * A_STRIDE;
    const int a_rsw = a_row & 7;           // +16 preserves &7
    const int a_ulane = (lane >> 4);
    const uint32_t B_lane = (uint32_t)(warp_n * 64 + ((lane >> 4) << 3) + (lane & 7)) * B_STRIDE
                          + (uint32_t)((lane >> 3) & 1) * 16;
    const uint32_t Bb0 = smb_B + B_lane;            // stage 0 frag base
    const uint32_t Bb1 = smb_B + B_CHUNK + B_lane;  // stage 1 frag base

    float acc[2][8][4];
    #pragma unroll
    for (int i = 0; i < 2; i++)
        #pragma unroll
        for (int j = 0; j < 8; j++)
            #pragma unroll
            for (int l = 0; l < 4; l++) acc[i][j][l] = 0.0f;

    CP_WAIT0();        // chunks 0,1 landed (covered by phase 1)
    __syncthreads();   // A panel + B stages visible

    // Preload B frags for chunk 0 from stage 0
    uint32_t bfA[4][4], bfB[4][4];
    #pragma unroll
    for (int ntp = 0; ntp < 4; ntp++)
        ldsm4(bfA[ntp], Bb0 + ntp * (16 * B_STRIDE));

    // RACE FIX (R14 bug): order every warp's preload reads of stage 0
    // before any warp's iter-0 cp.async overwrite of stage 0.
    __syncthreads();

    // wrap-around loop state
    const __half* wp = wt0 + 32;   // prefetch source for chunk 2
    int pk     = 2;                // prefetch k-chunk within n-tile
    int kc     = 0;                // k-chunk of current (MMA) chunk
    int n0cur  = 0;                // current n-tile base column
    int remain = NCHUNK - 2;

    // body: iteration m. cur frags = CUR (chunk m); loads NXT <- chunk m+1
    // from stage SN; prefetches chunk m+2 into stage SC (= m%2).
#define BODY(CUR, NXT, BCUR_SC, BNXT_SN)                                       \
    {                                                                          \
        if (remain > 0) {                                                      \
            remain--;                                                          \
            cp_async16((BCUR_SC) - B_lane + d0,                  wp);          \
            cp_async16((BCUR_SC) - B_lane + d0 + 128 * B_STRIDE,               \
                       wp + (size_t)128 * II);                                 \
            wp += 16;                                                          \
            if (++pk == KCH) { pk = 0; wp += (size_t)256 * II - 640; }         \
        }                                                                      \
        CP_COMMIT();                                                           \
        /* A frags for chunk m (panel is static) */                            \
        const int u = kc * 2 + a_ulane;                                        \
        const uint32_t a_off = (uint32_t)((u ^ a_rsw) << 4);                   \
        uint32_t a0[4], a1[4];                                                 \
        ldsm4(a0, A_row0 + a_off);                                             \
        ldsm4(a1, A_row1 + a_off);                                             \
        /* B frags for chunk m+1 (stage SN, landed by last wait0+sync) */      \
        _Pragma("unroll")                                                      \
        for (int ntp = 0; ntp < 4; ntp++)                                      \
            ldsm4(NXT[ntp], (BNXT_SN) + ntp * (16 * B_STRIDE));                \
        /* MMA chunk m with register-resident CUR frags */                     \
        _Pragma("unroll")                                                      \
        for (int ntp = 0; ntp < 4; ntp++) {                                    \
            mma16816(acc[0][2 * ntp + 0], a0[0], a0[1], a0[2], a0[3],          \
                     CUR[ntp][0], CUR[ntp][1]);                                \
            mma16816(acc[0][2 * ntp + 1], a0[0], a0[1], a0[2], a0[3],          \
                     CUR[ntp][2], CUR[ntp][3]);                                \
            mma16816(acc[1][2 * ntp + 0], a1[0], a1[1], a1[2], a1[3],          \
                     CUR[ntp][0], CUR[ntp][1]);                                \
            mma16816(acc[1][2 * ntp + 1], a1[0], a1[1], a1[2], a1[3],          \
                     CUR[ntp][2], CUR[ntp][3]);                                \
        }                                                                      \
        if (kc == KCH - 1) {                                                   \
            _Pragma("unroll")                                                  \
            for (int mt = 0; mt < 2; mt++) {                                   \
                const int r = warp_m * 32 + mt * 16 + (lane >> 2);             \
                float* o0 = out + ((size_t)bt * 128 + urow0 + r) * VV;         \
                _Pragma("unroll")                                              \
                for (int nt = 0; nt < 8; nt++) {                               \
                    const int col = n0cur + warp_n * 64 + nt * 8 + (lane & 3) * 2; \
                    float2 bb = *(const float2*)(dense_b + col);               \
                    float2 v0 = make_float2(acc[mt][nt][0] + bb.x,             \
                                            acc[mt][nt][1] + bb.y);            \
                    float2 v1 = make_float2(acc[mt][nt][2] + bb.x,             \
                                            acc[mt][nt][3] + bb.y);            \
                    *(float2*)(o0 + col) = v0;                                 \
                    *(float2*)(o0 + (size_t)8 * VV + col) = v1;                \
                    _Pragma("unroll")                                          \
                    for (int l = 0; l < 4; l++) acc[mt][nt][l] = 0.0f;         \
                }                                                              \
            }                                                                  \
            n0cur += 256;                                                      \
            kc = -1;                                                           \
        }                                                                      \
        kc++;                                                                  \
        CP_WAIT0();                                                            \
        __syncthreads();                                                       \
    }

    #pragma unroll 1
    for (int m = 0; m < NCHUNK; m += 2) {
        // even m: cur frags in bfA (chunk m, stage 0); next -> bfB (stage 1);
        //         prefetch m+2 -> stage 0.
        BODY(bfA, bfB, Bb0, Bb1)
        // odd m+1: cur bfB (stage 1); next -> bfA (stage 0); prefetch -> stage 1.
        BODY(bfB, bfA, Bb1, Bb0)
    }
#undef BODY
}

// ---------------------------------------------------------------------------
extern "C" void kernel_launch(void* const* d_in, const int* in_sizes, int n_in,
                              void* d_out, int out_size) {
    const float* enc_h   = (const float*)d_in[0];
    const float* dec_h   = (const float*)d_in[1];
    const float* enc_w   = (const float*)d_in[2];
    const float* enc_b   = (const float*)d_in[3];
    const float* dec_w   = (const float*)d_in[4];
    const float* dec_b   = (const float*)d_in[5];
    const float* dense_w = (const float*)d_in[6];
    const float* dense_b = (const float*)d_in[7];
    float* out = (float*)d_out;

    static bool attr_set = false;
    if (!attr_set) {
        cudaFuncSetAttribute(joint_mma_kernel,
                             cudaFuncAttributeMaxDynamicSharedMemorySize, DYN_SMEM);
        attr_set = true;
    }

    proj_kernel<<<dim3(10, 96), 128>>>(enc_h, dec_h, enc_w, enc_b, dec_w, dec_b);
    wsplit_kernel<<<640, 256>>>(dense_w);
    // 4096 CTAs: (bt, u-half); each covers full V. 2 CTAs resident per SM.
    joint_mma_kernel<<<4096, 256, DYN_SMEM>>>(dense_b, out);
}